// round 11
// baseline (speedup 1.0000x reference)
#include <cuda_runtime.h>
#include <math.h>

#define Bq 16
#define Sq 2048
#define Hq 512
#define Oq 16
#define BSq (Bq*Sq)            // 32768
#define RSQRT_H 0.04419417382415922f   // 1/sqrt(512)

typedef unsigned long long ull;
typedef unsigned int uint;

__device__ __forceinline__ ull ffma2(ull a, ull b, ull c) {
    ull d; asm("fma.rn.f32x2 %0, %1, %2, %3;" : "=l"(d) : "l"(a), "l"(b), "l"(c));
    return d;
}
__device__ __forceinline__ ull dup2(float f) {
    ull r; asm("mov.b64 %0, {%1, %1};" : "=l"(r) : "f"(f));
    return r;
}

// tf32 m16n8k8 mma, D += A*B (D,C aliased)
__device__ __forceinline__ void mma_tf32(float& d0, float& d1, float& d2, float& d3,
                                         uint a0, uint a1, uint a2, uint a3,
                                         uint b0, uint b1) {
    asm volatile("mma.sync.aligned.m16n8k8.row.col.f32.tf32.tf32.f32 "
        "{%0,%1,%2,%3}, {%4,%5,%6,%7}, {%8,%9}, {%0,%1,%2,%3};"
        : "+f"(d0), "+f"(d1), "+f"(d2), "+f"(d3)
        : "r"(a0), "r"(a1), "r"(a2), "r"(a3), "r"(b0), "r"(b1));
}

// ---------------- scratch (device globals) ----------------------------------
__device__ float g_oq[Oq*Hq];              // raw operator queries (atomic accum)
__device__ float g_kq[Oq*Hq];              // oq @ Wk, pre-scaled  [o][k]
__device__ float g_c[Oq];                  // bk . oq, pre-scaled
__device__ float g_logits[BSq*Oq];         // [b][s][o] (K-half 0 partial, then final)
__device__ float g_lp2[BSq*Oq];            // K-half 1 partial
__device__ float g_esum[Bq*Oq];            // sum_s exp(logits)  (atomic)
__device__ float g_W[Bq*Oq];               // sum_s w (normalized, atomic)
__device__ float g_up[16*Bq*Oq*Hq];        // split-s partials of u (normalized)
__device__ float g_u[Bq*Oq*Hq];            // sum_s w * x (normalized)
__device__ float g_opout[Bq*Oq*Hq];        // operator outputs

// ---------------- K-zero -----------------------------------------------------
__global__ void kzero() {
    int i = blockIdx.x * 256 + threadIdx.x;
    if (i < Oq*Hq) g_oq[i] = 0.f;
    if (i < Bq*Oq) { g_esum[i] = 0.f; g_W[i] = 0.f; }
}

// ---------------- K0a: oq[o][h] = sum_s ops[s][o] * Wq_op[h][s] --------------
__global__ void __launch_bounds__(512) k0a(const float* __restrict__ Wq_op,
                                           const float* __restrict__ ops) {
    __shared__ float ops_sh[128*16];
    __shared__ float wq_sh[64][129];
    int h0 = blockIdx.x * 64, s0 = blockIdx.y * 128;
    for (int i = threadIdx.x; i < 128*16; i += 512)
        ops_sh[i] = ops[s0*16 + i];
    for (int i = threadIdx.x; i < 64*128; i += 512) {
        int r = i >> 7, c = i & 127;
        wq_sh[r][c] = Wq_op[(size_t)(h0 + r)*Sq + s0 + c];
    }
    __syncthreads();
    int hl = threadIdx.x & 63;
    int og = threadIdx.x >> 6;
    float a0 = 0.f, a1 = 0.f;
    #pragma unroll 8
    for (int s = 0; s < 128; s++) {
        float wv = wq_sh[hl][s];
        a0 += wv * ops_sh[s*16 + og*2];
        a1 += wv * ops_sh[s*16 + og*2 + 1];
    }
    atomicAdd(&g_oq[(og*2    )*Hq + h0 + hl], a0);
    atomicAdd(&g_oq[(og*2 + 1)*Hq + h0 + hl], a1);
}

// ---------------- K0b: kq[o][k] = (oq+bq)@Wk * rs; c = bk.(oq+bq)*rs ---------
__global__ void __launch_bounds__(128) k0b(const float* __restrict__ Wk,
                                           const float* __restrict__ bk,
                                           const float* __restrict__ bq,
                                           float* oq_out) {
    __shared__ float oq_sh[Hq];
    __shared__ float red[4][33];
    __shared__ float cr[128];
    int o = blockIdx.x, kc = blockIdx.y;
    for (int h = threadIdx.x; h < Hq; h += 128) {
        float v = g_oq[o*Hq + h] + bq[h];
        oq_sh[h] = v;
        if (kc == 0 && oq_out) oq_out[o*Hq + h] = v;
    }
    __syncthreads();
    int kl = threadIdx.x & 31, hq = threadIdx.x >> 5;
    int k = kc*32 + kl;
    const float* wp = Wk + (size_t)(hq*128)*Hq + k;
    float a = 0.f;
    #pragma unroll 16
    for (int h = 0; h < 128; h++)
        a += oq_sh[hq*128 + h] * wp[(size_t)h*Hq];
    red[hq][kl] = a;
    __syncthreads();
    if (hq == 0)
        g_kq[o*Hq + k] = (red[0][kl] + red[1][kl] + red[2][kl] + red[3][kl]) * RSQRT_H;
    if (kc == 0) {
        float cl = 0.f;
        for (int h = threadIdx.x; h < Hq; h += 128) cl += bk[h] * oq_sh[h];
        cr[threadIdx.x] = cl;
        __syncthreads();
        for (int st = 64; st > 0; st >>= 1) {
            if (threadIdx.x < st) cr[threadIdx.x] += cr[threadIdx.x + st];
            __syncthreads();
        }
        if (threadIdx.x == 0) g_c[o] = cr[0] * RSQRT_H;
    }
}

// ---------------- K1: partial logits via tf32 MMA, K split in halves --------
// grid 512: blockIdx = rowblk*2 + kh. 256 thr = 8 warps x 16 rows = 128 rows.
// kq half pre-split hi/lo in smem (no B-split ALU in loop). 32-col x chunks,
// register prefetch. smem = 58.5KB -> 3 CTAs/SM -> 24 warps/SM.
#define SM_KQH 0                     // 16 x 260
#define SM_KQL 4160                  // 16 x 260
#define SM_ST  8320                  // 128 x 16
#define SM_X   10368                 // 8 warps x (16 x 36)
#define SM_FLOATS (10368 + 8*576)    // 14976 floats = 59904 bytes

__global__ void __launch_bounds__(256, 3) k1(const float* __restrict__ x) {
    extern __shared__ float sm[];
    float* kqh = sm + SM_KQH;
    float* kql = sm + SM_KQL;
    float* st  = sm + SM_ST;
    int tid = threadIdx.x, wid = tid >> 5, lane = tid & 31;
    int lg = lane >> 2, lr = lane & 3;
    int kh = blockIdx.x & 1;
    size_t rowblk = (size_t)(blockIdx.x >> 1);

    // stage this K-half of kq, pre-split into hi/lo
    for (int f = tid; f < 16*256; f += 256) {
        int row = f >> 8, c = f & 255;
        float v = g_kq[row*512 + kh*256 + c];
        uint h = __float_as_uint(v) & 0xFFFFE000u;
        kqh[row*260 + c] = __uint_as_float(h);
        kql[row*260 + c] = v - __uint_as_float(h);
    }
    __syncthreads();

    size_t row0 = rowblk * 128 + wid * 16;
    float* xw = sm + SM_X + wid * 576;      // 16 x 36

    float D1[2][4] = {{0.f,0.f,0.f,0.f},{0.f,0.f,0.f,0.f}};
    float D2[2][4] = {{0.f,0.f,0.f,0.f},{0.f,0.f,0.f,0.f}};
    float D3[2][4] = {{0.f,0.f,0.f,0.f},{0.f,0.f,0.f,0.f}};

    // x chunks: 16 rows x 32 cols (8 float4/row). lane -> (rowp, c4p)
    const float4* xg = (const float4*)x + row0*128 + kh*64;
    int rowp = lane >> 3, c4p = lane & 7;
    float4 pf[4];
    #pragma unroll
    for (int t = 0; t < 4; t++)
        pf[t] = xg[(size_t)(rowp + t*4)*128 + c4p];

    for (int kc = 0; kc < 8; kc++) {
        #pragma unroll
        for (int t = 0; t < 4; t++)
            ((float4*)(xw + (rowp + t*4)*36))[c4p] = pf[t];
        __syncwarp();
        if (kc < 7) {
            const float4* xn = xg + (kc + 1)*8;
            #pragma unroll
            for (int t = 0; t < 4; t++)
                pf[t] = xn[(size_t)(rowp + t*4)*128 + c4p];
        }

        #pragma unroll
        for (int kk = 0; kk < 4; kk++) {
            // A fragments (x), rows lg / lg+8, k-cols lr / lr+4; split in regs
            int ab = lg*36 + kk*8 + lr;
            float a0 = xw[ab],           a1 = xw[ab + 8*36];
            float a2 = xw[ab + 4],       a3 = xw[ab + 8*36 + 4];
            uint ah0 = __float_as_uint(a0) & 0xFFFFE000u;
            uint ah1 = __float_as_uint(a1) & 0xFFFFE000u;
            uint ah2 = __float_as_uint(a2) & 0xFFFFE000u;
            uint ah3 = __float_as_uint(a3) & 0xFFFFE000u;
            uint al0 = __float_as_uint(a0 - __uint_as_float(ah0));
            uint al1 = __float_as_uint(a1 - __uint_as_float(ah1));
            uint al2 = __float_as_uint(a2 - __uint_as_float(ah2));
            uint al3 = __float_as_uint(a3 - __uint_as_float(ah3));
            // B fragments pre-split in smem
            int bb = lg*260 + kc*32 + kk*8 + lr;
            uint bh00 = __float_as_uint(kqh[bb]);
            uint bh10 = __float_as_uint(kqh[bb + 4]);
            uint bh01 = __float_as_uint(kqh[bb + 8*260]);
            uint bh11 = __float_as_uint(kqh[bb + 8*260 + 4]);
            uint bl00 = __float_as_uint(kql[bb]);
            uint bl10 = __float_as_uint(kql[bb + 4]);
            uint bl01 = __float_as_uint(kql[bb + 8*260]);
            uint bl11 = __float_as_uint(kql[bb + 8*260 + 4]);

            mma_tf32(D1[0][0],D1[0][1],D1[0][2],D1[0][3], ah0,ah1,ah2,ah3, bh00,bh10);
            mma_tf32(D2[0][0],D2[0][1],D2[0][2],D2[0][3], al0,al1,al2,al3, bh00,bh10);
            mma_tf32(D3[0][0],D3[0][1],D3[0][2],D3[0][3], ah0,ah1,ah2,ah3, bl00,bl10);
            mma_tf32(D1[1][0],D1[1][1],D1[1][2],D1[1][3], ah0,ah1,ah2,ah3, bh01,bh11);
            mma_tf32(D2[1][0],D2[1][1],D2[1][2],D2[1][3], al0,al1,al2,al3, bh01,bh11);
            mma_tf32(D3[1][0],D3[1][1],D3[1][2],D3[1][3], ah0,ah1,ah2,ah3, bl01,bl11);
        }
        __syncwarp();
    }

    // D -> st:  row = wid*16 + lg (+8), col = h*8 + 2*lr (+1)
    #pragma unroll
    for (int h = 0; h < 2; h++) {
        float d0 = D1[h][0] + D2[h][0] + D3[h][0];
        float d1 = D1[h][1] + D2[h][1] + D3[h][1];
        float d2 = D1[h][2] + D2[h][2] + D3[h][2];
        float d3 = D1[h][3] + D2[h][3] + D3[h][3];
        int r = wid*16 + lg, c = h*8 + 2*lr;
        st[r*16 + c]         = d0;
        st[r*16 + c + 1]     = d1;
        st[(r+8)*16 + c]     = d2;
        st[(r+8)*16 + c + 1] = d3;
    }
    __syncthreads();

    // write partial (no +c, no esum) to the half buffer, coalesced
    float* dst = kh ? g_lp2 : g_logits;
    size_t gb = rowblk * 2048;
    #pragma unroll
    for (int t = 0; t < 8; t++)
        dst[gb + t*256 + tid] = st[t*256 + tid];
}

// ---------------- K1e: combine K-halves, +c, esum ----------------------------
// grid 64 x 512 thr; block covers 8192 floats; 4 blocks per batch
__global__ void __launch_bounds__(512) k1e() {
    __shared__ float red[32][17];
    int tid = threadIdx.x, o = tid & 15;
    size_t base = (size_t)blockIdx.x * 8192;
    float cc = g_c[o];
    float es = 0.f;
    #pragma unroll 4
    for (int t = 0; t < 16; t++) {
        size_t i = base + t*512 + tid;
        float v = g_logits[i] + g_lp2[i] + cc;
        g_logits[i] = v;
        es += __expf(v);
    }
    red[tid >> 4][o] = es;
    __syncthreads();
    if (tid < 16) {
        float s = 0.f;
        #pragma unroll
        for (int j = 0; j < 32; j++) s += red[j][tid];
        atomicAdd(&g_esum[(blockIdx.x >> 2)*16 + tid], s);
    }
}

// ---------------- K2: split-s partials of u = sum_s w*x (w normalized) ------
__global__ void __launch_bounds__(256) k2(const float* __restrict__ x,
                                          const float* __restrict__ ops) {
    __shared__ __align__(16) float w_sh[128*16];   // 8KB
    __shared__ float inv_sh[16];
    __shared__ float wr[16][17];
    int sc = blockIdx.x, b = blockIdx.y;
    int tid = threadIdx.x;
    int s0 = sc * 128;
    if (tid < 16) inv_sh[tid] = 1.0f / g_esum[b*16 + tid];
    __syncthreads();
    const float* L  = g_logits + ((size_t)b*Sq + s0)*16;
    const float* op = ops + (size_t)s0*16;
    float Wloc = 0.f;
    #pragma unroll
    for (int t = 0; t < 8; t++) {
        int i = t*256 + tid;
        float wv = __expf(L[i]) * inv_sh[i & 15] * op[i];
        w_sh[i] = wv;
        Wloc += wv;
    }
    wr[tid >> 4][tid & 15] = Wloc;
    __syncthreads();
    if (tid < 16) {
        float s = 0.f;
        #pragma unroll
        for (int j = 0; j < 16; j++) s += wr[j][tid];
        atomicAdd(&g_W[b*16 + tid], s);
    }
    const float* xq = x + ((size_t)b*Sq + s0)*Hq + tid;
    ull a0[8], a1[8];
    #pragma unroll
    for (int j = 0; j < 8; j++) { a0[j] = 0ull; a1[j] = 0ull; }
    #pragma unroll 8
    for (int s = 0; s < 128; s++) {
        float xv0 = xq[(size_t)s*Hq];
        float xv1 = xq[(size_t)s*Hq + 256];
        ull xa = dup2(xv0), xb = dup2(xv1);
        const ull* w8 = (const ull*)(w_sh + s*16);
        #pragma unroll
        for (int j = 0; j < 8; j++) {
            ull wv = w8[j];
            a0[j] = ffma2(xa, wv, a0[j]);
            a1[j] = ffma2(xb, wv, a1[j]);
        }
    }
    float* up = g_up + (size_t)(sc*16 + b)*16*512;
    #pragma unroll
    for (int j = 0; j < 8; j++) {
        float lo, hi;
        asm("mov.b64 {%0,%1}, %2;" : "=f"(lo), "=f"(hi) : "l"(a0[j]));
        up[(2*j)*512 + tid]         = lo;
        up[(2*j+1)*512 + tid]       = hi;
        asm("mov.b64 {%0,%1}, %2;" : "=f"(lo), "=f"(hi) : "l"(a1[j]));
        up[(2*j)*512 + tid + 256]   = lo;
        up[(2*j+1)*512 + tid + 256] = hi;
    }
}

// ---------------- Ksum: u = sum of 16 split-s partials -----------------------
__global__ void ksum() {
    int i = blockIdx.x*256 + threadIdx.x;   // 32768 float4s
    int b = i >> 11, w4 = i & 2047;
    const float4* up4 = (const float4*)g_up;
    float4 s = up4[(size_t)b*2048 + w4];
    #pragma unroll
    for (int p = 1; p < 16; p++) {
        float4 t = up4[(size_t)(p*16 + b)*2048 + w4];
        s.x += t.x; s.y += t.y; s.z += t.z; s.w += t.w;
    }
    ((float4*)g_u)[i] = s;
}

// fold-reduce 16 floats over 32 lanes; lane l (<16) ends holding total of v[l]
__device__ __forceinline__ float fold16(float v[16], int lane) {
    #pragma unroll
    for (int i = 0; i < 16; i++)
        v[i] += __shfl_xor_sync(0xffffffffu, v[i], 16);
    #pragma unroll
    for (int i = 0; i < 8; i++) {
        float mn = (lane & 8) ? v[i+8] : v[i];
        float th = (lane & 8) ? v[i] : v[i+8];
        v[i] = mn + __shfl_xor_sync(0xffffffffu, th, 8);
    }
    #pragma unroll
    for (int i = 0; i < 4; i++) {
        float mn = (lane & 4) ? v[i+4] : v[i];
        float th = (lane & 4) ? v[i] : v[i+4];
        v[i] = mn + __shfl_xor_sync(0xffffffffu, th, 4);
    }
    #pragma unroll
    for (int i = 0; i < 2; i++) {
        float mn = (lane & 2) ? v[i+2] : v[i];
        float th = (lane & 2) ? v[i] : v[i+2];
        v[i] = mn + __shfl_xor_sync(0xffffffffu, th, 2);
    }
    {
        float mn = (lane & 1) ? v[1] : v[0];
        float th = (lane & 1) ? v[0] : v[1];
        v[0] = mn + __shfl_xor_sync(0xffffffffu, th, 1);
    }
    return v[0];
}

// ---------------- K3: op_out[b,o,h] = u[b,o,:].Wv[h,:] + bv[h]*W[b,o] -------
__global__ void __launch_bounds__(256) k3(const float* __restrict__ Wv,
                                          const float* __restrict__ bv) {
    __shared__ float4 u4[16*128];
    __shared__ float Wsh[16];
    int o = blockIdx.x, hc = blockIdx.y;
    for (int i = threadIdx.x; i < 16*128; i += 256) {
        int b = i >> 7, k4 = i & 127;
        u4[i] = ((const float4*)g_u)[((size_t)b*16 + o)*128 + k4];
    }
    if (threadIdx.x < 16) Wsh[threadIdx.x] = g_W[threadIdx.x*16 + o];
    __syncthreads();
    int wid = threadIdx.x >> 5, lane = threadIdx.x & 31;
    for (int q = 0; q < 2; q++) {
        int h = hc*64 + wid*8 + q*4;
        const float4* wv = ((const float4*)Wv) + (size_t)h * 128;
        float acc[4][16];
        #pragma unroll
        for (int r = 0; r < 4; r++)
            #pragma unroll
            for (int b = 0; b < 16; b++) acc[r][b] = 0.f;
        #pragma unroll
        for (int jj = 0; jj < 4; jj++) {
            int j = jj*32 + lane;
            float4 v0 = wv[j], v1 = wv[128+j], v2 = wv[256+j], v3 = wv[384+j];
            #pragma unroll
            for (int b = 0; b < 16; b++) {
                float4 uu = u4[b*128 + j];
                acc[0][b] += v0.x*uu.x + v0.y*uu.y + v0.z*uu.z + v0.w*uu.w;
                acc[1][b] += v1.x*uu.x + v1.y*uu.y + v1.z*uu.z + v1.w*uu.w;
                acc[2][b] += v2.x*uu.x + v2.y*uu.y + v2.z*uu.z + v2.w*uu.w;
                acc[3][b] += v3.x*uu.x + v3.y*uu.y + v3.z*uu.z + v3.w*uu.w;
            }
        }
        #pragma unroll
        for (int r = 0; r < 4; r++) {
            float t = fold16(acc[r], lane);
            if (lane < 16)
                g_opout[((size_t)lane*16 + o)*Hq + h + r] = t + bv[h + r] * Wsh[lane];
        }
    }
}

// ---------------- K4: out[b,s,h] = sum_o softmax_o(L)[o]*op_out[b,o,h] ------
__global__ void __launch_bounds__(256) k4(float* __restrict__ out) {
    __shared__ __align__(16) float4 op4[16*128];
    int b = blockIdx.y, sc = blockIdx.x;
    for (int i = threadIdx.x; i < 16*128; i += 256)
        op4[i] = ((const float4*)g_opout)[(size_t)b*2048 + i];
    __syncthreads();
    int wid = threadIdx.x >> 5, lane = threadIdx.x & 31;
    for (int q = 0; q < 2; q++) {
        int s0 = sc*64 + wid*8 + q*4;
        size_t r0 = (size_t)b*Sq + s0;
        const float* lp = g_logits + (r0 + (lane & 3)) * 16;
        float e[16];
        float mx = -1e30f;
        #pragma unroll
        for (int o = 0; o < 16; o++) { e[o] = lp[o]; mx = fmaxf(mx, e[o]); }
        float sum = 0.f;
        #pragma unroll
        for (int o = 0; o < 16; o++) { e[o] = __expf(e[o] - mx); sum += e[o]; }
        float inv = 1.0f / sum;
        float ow0[16], ow1[16], ow2[16], ow3[16];
        #pragma unroll
        for (int o = 0; o < 16; o++) {
            float v = e[o] * inv;
            ow0[o] = __shfl_sync(0xffffffffu, v, 0, 4);
            ow1[o] = __shfl_sync(0xffffffffu, v, 1, 4);
            ow2[o] = __shfl_sync(0xffffffffu, v, 2, 4);
            ow3[o] = __shfl_sync(0xffffffffu, v, 3, 4);
        }
        ulonglong2* o2 = (ulonglong2*)(((float4*)out) + r0 * 128);
        #pragma unroll
        for (int jj = 0; jj < 4; jj++) {
            int j = jj*32 + lane;
            ull A0[2] = {0ull,0ull}, A1[2] = {0ull,0ull};
            ull A2[2] = {0ull,0ull}, A3[2] = {0ull,0ull};
            #pragma unroll
            for (int o = 0; o < 16; o++) {
                ulonglong2 kk = ((const ulonglong2*)op4)[o*128 + j];
                ull d0 = dup2(ow0[o]), d1 = dup2(ow1[o]);
                ull d2 = dup2(ow2[o]), d3 = dup2(ow3[o]);
                A0[0] = ffma2(d0, kk.x, A0[0]); A0[1] = ffma2(d0, kk.y, A0[1]);
                A1[0] = ffma2(d1, kk.x, A1[0]); A1[1] = ffma2(d1, kk.y, A1[1]);
                A2[0] = ffma2(d2, kk.x, A2[0]); A2[1] = ffma2(d2, kk.y, A2[1]);
                A3[0] = ffma2(d3, kk.x, A3[0]); A3[1] = ffma2(d3, kk.y, A3[1]);
            }
            o2[j]        = make_ulonglong2(A0[0], A0[1]);
            o2[128 + j]  = make_ulonglong2(A1[0], A1[1]);
            o2[256 + j]  = make_ulonglong2(A2[0], A2[1]);
            o2[384 + j]  = make_ulonglong2(A3[0], A3[1]);
        }
    }
}

// ---------------------------------------------------------------------------
extern "C" void kernel_launch(void* const* d_in, const int* in_sizes, int n_in,
                              void* d_out, int out_size) {
    const float* x     = (const float*)d_in[0];
    const float* Wv    = (const float*)d_in[1];
    const float* bv    = (const float*)d_in[2];
    const float* Wk    = (const float*)d_in[3];
    const float* bk    = (const float*)d_in[4];
    const float* Wq_op = (const float*)d_in[5];
    const float* bq_op = (const float*)d_in[6];
    const float* ops   = (const float*)d_in[7];
    (void)in_sizes; (void)n_in;
    float* out = (float*)d_out;
    float* oq_out = (out_size >= Bq*Sq*Hq + Oq*Hq) ? out + (size_t)Bq*Sq*Hq : nullptr;

    cudaFuncSetAttribute(k1, cudaFuncAttributeMaxDynamicSharedMemorySize,
                         SM_FLOATS * (int)sizeof(float));

    kzero<<<32, 256>>>();
    k0a<<<dim3(8, 16), 512>>>(Wq_op, ops);
    k0b<<<dim3(16, 16), 128>>>(Wk, bk, bq_op, oq_out);
    k1<<<512, 256, SM_FLOATS * sizeof(float)>>>(x);
    k1e<<<64, 512>>>();
    k2<<<dim3(16, 16), 256>>>(x, ops);
    ksum<<<128, 256>>>();
    k3<<<dim3(16, 8), 256>>>(Wv, bv);
    k4<<<dim3(32, 16), 256>>>(out);
}

// round 12
// speedup vs baseline: 1.1855x; 1.1855x over previous
#include <cuda_runtime.h>
#include <math.h>

#define Bq 16
#define Sq 2048
#define Hq 512
#define Oq 16
#define BSq (Bq*Sq)            // 32768
#define RSQRT_H 0.04419417382415922f   // 1/sqrt(512)

typedef unsigned long long ull;
typedef unsigned int uint;

__device__ __forceinline__ ull ffma2(ull a, ull b, ull c) {
    ull d; asm("fma.rn.f32x2 %0, %1, %2, %3;" : "=l"(d) : "l"(a), "l"(b), "l"(c));
    return d;
}
__device__ __forceinline__ ull dup2(float f) {
    ull r; asm("mov.b64 %0, {%1, %1};" : "=l"(r) : "f"(f));
    return r;
}

// tf32 m16n8k8 mma, D += A*B (D,C aliased)
__device__ __forceinline__ void mma_tf32(float& d0, float& d1, float& d2, float& d3,
                                         uint a0, uint a1, uint a2, uint a3,
                                         uint b0, uint b1) {
    asm volatile("mma.sync.aligned.m16n8k8.row.col.f32.tf32.tf32.f32 "
        "{%0,%1,%2,%3}, {%4,%5,%6,%7}, {%8,%9}, {%0,%1,%2,%3};"
        : "+f"(d0), "+f"(d1), "+f"(d2), "+f"(d3)
        : "r"(a0), "r"(a1), "r"(a2), "r"(a3), "r"(b0), "r"(b1));
}

// ---------------- scratch (device globals) ----------------------------------
__device__ float g_oq[Oq*Hq];              // raw operator queries (atomic accum)
__device__ float g_kq[Oq*Hq];              // oq @ Wk, pre-scaled  [o][k]
__device__ float g_c[Oq];                  // bk . oq, pre-scaled
__device__ float g_logits[BSq*Oq];         // [b][s][o]
__device__ float g_esum[Bq*Oq];            // sum_s exp(logits)  (atomic)
__device__ float g_W[Bq*Oq];               // sum_s w (normalized, atomic)
__device__ float g_up[32*Bq*Oq*Hq];        // split-s partials of u (normalized)
__device__ float g_u[Bq*Oq*Hq];            // sum_s w * x (normalized)
__device__ float g_opout[Bq*Oq*Hq];        // operator outputs

// ---------------- K-zero -----------------------------------------------------
__global__ void kzero() {
    int i = blockIdx.x * 256 + threadIdx.x;
    if (i < Oq*Hq) g_oq[i] = 0.f;
    if (i < Bq*Oq) { g_esum[i] = 0.f; g_W[i] = 0.f; }
}

// ---------------- K0a: oq[o][h] = sum_s ops[s][o] * Wq_op[h][s] --------------
__global__ void __launch_bounds__(512) k0a(const float* __restrict__ Wq_op,
                                           const float* __restrict__ ops) {
    __shared__ float ops_sh[128*16];
    __shared__ float wq_sh[64][129];
    int h0 = blockIdx.x * 64, s0 = blockIdx.y * 128;
    for (int i = threadIdx.x; i < 128*16; i += 512)
        ops_sh[i] = ops[s0*16 + i];
    for (int i = threadIdx.x; i < 64*128; i += 512) {
        int r = i >> 7, c = i & 127;
        wq_sh[r][c] = Wq_op[(size_t)(h0 + r)*Sq + s0 + c];
    }
    __syncthreads();
    int hl = threadIdx.x & 63;
    int og = threadIdx.x >> 6;
    float a0 = 0.f, a1 = 0.f;
    #pragma unroll 8
    for (int s = 0; s < 128; s++) {
        float wv = wq_sh[hl][s];
        a0 += wv * ops_sh[s*16 + og*2];
        a1 += wv * ops_sh[s*16 + og*2 + 1];
    }
    atomicAdd(&g_oq[(og*2    )*Hq + h0 + hl], a0);
    atomicAdd(&g_oq[(og*2 + 1)*Hq + h0 + hl], a1);
}

// ---------------- K0b: kq[o][k] = (oq+bq)@Wk * rs; c = bk.(oq+bq)*rs ---------
__global__ void __launch_bounds__(128) k0b(const float* __restrict__ Wk,
                                           const float* __restrict__ bk,
                                           const float* __restrict__ bq,
                                           float* oq_out) {
    __shared__ float oq_sh[Hq];
    __shared__ float red[4][33];
    __shared__ float cr[128];
    int o = blockIdx.x, kc = blockIdx.y;
    for (int h = threadIdx.x; h < Hq; h += 128) {
        float v = g_oq[o*Hq + h] + bq[h];
        oq_sh[h] = v;
        if (kc == 0 && oq_out) oq_out[o*Hq + h] = v;
    }
    __syncthreads();
    int kl = threadIdx.x & 31, hq = threadIdx.x >> 5;
    int k = kc*32 + kl;
    const float* wp = Wk + (size_t)(hq*128)*Hq + k;
    float a = 0.f;
    #pragma unroll 16
    for (int h = 0; h < 128; h++)
        a += oq_sh[hq*128 + h] * wp[(size_t)h*Hq];
    red[hq][kl] = a;
    __syncthreads();
    if (hq == 0)
        g_kq[o*Hq + k] = (red[0][kl] + red[1][kl] + red[2][kl] + red[3][kl]) * RSQRT_H;
    if (kc == 0) {
        float cl = 0.f;
        for (int h = threadIdx.x; h < Hq; h += 128) cl += bk[h] * oq_sh[h];
        cr[threadIdx.x] = cl;
        __syncthreads();
        for (int st = 64; st > 0; st >>= 1) {
            if (threadIdx.x < st) cr[threadIdx.x] += cr[threadIdx.x + st];
            __syncthreads();
        }
        if (threadIdx.x == 0) g_c[o] = cr[0] * RSQRT_H;
    }
}

// ---------------- K1: logits = x.kq + c via tf32 MMA (split precision) ------
// R10 version: 128 threads = 4 warps, 64 rows/block, 32-col x chunks + prefetch
#define SM_KQ   0
#define SM_X    8256
#define SM_ST   (8256 + 4352)
#define SM_FLOATS (8256 + 4352 + 1024)      // 13632 floats = 54528 bytes

__global__ void __launch_bounds__(128) k1(const float* __restrict__ x) {
    extern __shared__ float sm[];
    float* kq_sh = sm + SM_KQ;
    float* st    = sm + SM_ST;
    __shared__ float c_sh[16];
    __shared__ float esr[8][17];
    int tid = threadIdx.x, wid = tid >> 5, lane = tid & 31;
    int lg = lane >> 2, lr = lane & 3;

    // stage kq (16 x 512 -> rows padded to 516)
    for (int f = tid; f < 2048; f += 128) {
        int row = f >> 7, c4 = f & 127;
        float4 v = ((const float4*)g_kq)[row*128 + c4];
        ((float4*)(kq_sh + row*516))[c4] = v;
    }
    if (tid < 16) c_sh[tid] = g_c[tid];
    __syncthreads();

    size_t row0 = (size_t)blockIdx.x * 64 + wid * 16;
    float* xw = sm + SM_X + wid * 1088;     // 16 x 68

    float D1[2][4] = {{0.f,0.f,0.f,0.f},{0.f,0.f,0.f,0.f}};
    float D2[2][4] = {{0.f,0.f,0.f,0.f},{0.f,0.f,0.f,0.f}};
    float D3[2][4] = {{0.f,0.f,0.f,0.f},{0.f,0.f,0.f,0.f}};

    const float4* xg = (const float4*)x + row0*128;
    float4 pf[8];
    {
        int rowp = lane >> 4, c4p = lane & 15;
        #pragma unroll
        for (int t = 0; t < 8; t++)
            pf[t] = xg[(size_t)(rowp + t*2)*128 + c4p];
    }

    for (int kc = 0; kc < 8; kc++) {
        {
            int rowp = lane >> 4, c4p = lane & 15;
            #pragma unroll
            for (int t = 0; t < 8; t++)
                ((float4*)(xw + (rowp + t*2)*68))[c4p] = pf[t];
        }
        __syncwarp();
        if (kc < 7) {
            int rowp = lane >> 4, c4p = lane & 15;
            const float4* xn = xg + (kc + 1)*16;
            #pragma unroll
            for (int t = 0; t < 8; t++)
                pf[t] = xn[(size_t)(rowp + t*2)*128 + c4p];
        }

        #pragma unroll
        for (int kk = 0; kk < 8; kk++) {
            int ab = lg*68 + kk*8 + lr;
            float a0 = xw[ab],            a1 = xw[ab + 8*68];
            float a2 = xw[ab + 4],        a3 = xw[ab + 8*68 + 4];
            uint ah0 = __float_as_uint(a0) & 0xFFFFE000u;
            uint ah1 = __float_as_uint(a1) & 0xFFFFE000u;
            uint ah2 = __float_as_uint(a2) & 0xFFFFE000u;
            uint ah3 = __float_as_uint(a3) & 0xFFFFE000u;
            uint al0 = __float_as_uint(a0 - __uint_as_float(ah0));
            uint al1 = __float_as_uint(a1 - __uint_as_float(ah1));
            uint al2 = __float_as_uint(a2 - __uint_as_float(ah2));
            uint al3 = __float_as_uint(a3 - __uint_as_float(ah3));
            int bb = lg*516 + kc*64 + kk*8 + lr;
            float b00 = kq_sh[bb],          b10 = kq_sh[bb + 4];
            float b01 = kq_sh[bb + 8*516],  b11 = kq_sh[bb + 8*516 + 4];
            uint bh00 = __float_as_uint(b00) & 0xFFFFE000u;
            uint bh10 = __float_as_uint(b10) & 0xFFFFE000u;
            uint bh01 = __float_as_uint(b01) & 0xFFFFE000u;
            uint bh11 = __float_as_uint(b11) & 0xFFFFE000u;
            uint bl00 = __float_as_uint(b00 - __uint_as_float(bh00));
            uint bl10 = __float_as_uint(b10 - __uint_as_float(bh10));
            uint bl01 = __float_as_uint(b01 - __uint_as_float(bh01));
            uint bl11 = __float_as_uint(b11 - __uint_as_float(bh11));

            mma_tf32(D1[0][0],D1[0][1],D1[0][2],D1[0][3], ah0,ah1,ah2,ah3, bh00,bh10);
            mma_tf32(D2[0][0],D2[0][1],D2[0][2],D2[0][3], al0,al1,al2,al3, bh00,bh10);
            mma_tf32(D3[0][0],D3[0][1],D3[0][2],D3[0][3], ah0,ah1,ah2,ah3, bl00,bl10);
            mma_tf32(D1[1][0],D1[1][1],D1[1][2],D1[1][3], ah0,ah1,ah2,ah3, bh01,bh11);
            mma_tf32(D2[1][0],D2[1][1],D2[1][2],D2[1][3], al0,al1,al2,al3, bh01,bh11);
            mma_tf32(D3[1][0],D3[1][1],D3[1][2],D3[1][3], ah0,ah1,ah2,ah3, bl01,bl11);
        }
        __syncwarp();
    }

    #pragma unroll
    for (int h = 0; h < 2; h++) {
        float d0 = D1[h][0] + D2[h][0] + D3[h][0];
        float d1 = D1[h][1] + D2[h][1] + D3[h][1];
        float d2 = D1[h][2] + D2[h][2] + D3[h][2];
        float d3 = D1[h][3] + D2[h][3] + D3[h][3];
        int r = wid*16 + lg, c = h*8 + 2*lr;
        st[r*16 + c]         = d0;
        st[r*16 + c + 1]     = d1;
        st[(r+8)*16 + c]     = d2;
        st[(r+8)*16 + c + 1] = d3;
    }
    __syncthreads();

    float es = 0.f;
    size_t gb = (size_t)blockIdx.x * 1024;   // 64 rows * 16
    #pragma unroll
    for (int t = 0; t < 8; t++) {
        int i = tid + t*128;
        float v = st[i] + c_sh[i & 15];
        g_logits[gb + i] = v;
        es += __expf(v);
    }
    esr[tid >> 4][tid & 15] = es;
    __syncthreads();
    if (tid < 16) {
        float s = 0.f;
        #pragma unroll
        for (int j = 0; j < 8; j++) s += esr[j][tid];
        atomicAdd(&g_esum[(blockIdx.x >> 5)*16 + tid], s);
    }
}

// ---------------- K2: split-s partials of u = sum_s w*x (w normalized) ------
// grid (32 sc, 16 b), 256 threads; thread owns k=tid, tid+256; 64 s per block
__global__ void __launch_bounds__(256) k2(const float* __restrict__ x,
                                          const float* __restrict__ ops) {
    __shared__ __align__(16) float w_sh[64*16];    // 4KB
    __shared__ float inv_sh[16];
    __shared__ float wr[16][17];
    int sc = blockIdx.x, b = blockIdx.y;
    int tid = threadIdx.x;
    int s0 = sc * 64;
    if (tid < 16) inv_sh[tid] = 1.0f / g_esum[b*16 + tid];
    __syncthreads();
    const float* L  = g_logits + ((size_t)b*Sq + s0)*16;
    const float* op = ops + (size_t)s0*16;
    float Wloc = 0.f;
    #pragma unroll
    for (int t = 0; t < 4; t++) {
        int i = t*256 + tid;
        float wv = __expf(L[i]) * inv_sh[i & 15] * op[i];
        w_sh[i] = wv;
        Wloc += wv;
    }
    wr[tid >> 4][tid & 15] = Wloc;
    __syncthreads();
    if (tid < 16) {
        float s = 0.f;
        #pragma unroll
        for (int j = 0; j < 16; j++) s += wr[j][tid];
        atomicAdd(&g_W[b*16 + tid], s);
    }
    const float* xq = x + ((size_t)b*Sq + s0)*Hq + tid;
    ull a0[8], a1[8];
    #pragma unroll
    for (int j = 0; j < 8; j++) { a0[j] = 0ull; a1[j] = 0ull; }
    #pragma unroll 8
    for (int s = 0; s < 64; s++) {
        float xv0 = xq[(size_t)s*Hq];
        float xv1 = xq[(size_t)s*Hq + 256];
        ull xa = dup2(xv0), xb = dup2(xv1);
        const ull* w8 = (const ull*)(w_sh + s*16);
        #pragma unroll
        for (int j = 0; j < 8; j++) {
            ull wv = w8[j];
            a0[j] = ffma2(xa, wv, a0[j]);
            a1[j] = ffma2(xb, wv, a1[j]);
        }
    }
    float* up = g_up + (size_t)(sc*16 + b)*16*512;
    #pragma unroll
    for (int j = 0; j < 8; j++) {
        float lo, hi;
        asm("mov.b64 {%0,%1}, %2;" : "=f"(lo), "=f"(hi) : "l"(a0[j]));
        up[(2*j)*512 + tid]         = lo;
        up[(2*j+1)*512 + tid]       = hi;
        asm("mov.b64 {%0,%1}, %2;" : "=f"(lo), "=f"(hi) : "l"(a1[j]));
        up[(2*j)*512 + tid + 256]   = lo;
        up[(2*j+1)*512 + tid + 256] = hi;
    }
}

// ---------------- Ksum: u = sum of 32 split-s partials -----------------------
__global__ void ksum() {
    int i = blockIdx.x*256 + threadIdx.x;   // 32768 float4s
    int b = i >> 11, w4 = i & 2047;
    const float4* up4 = (const float4*)g_up;
    float4 s = up4[(size_t)b*2048 + w4];
    #pragma unroll 8
    for (int p = 1; p < 32; p++) {
        float4 t = up4[(size_t)(p*16 + b)*2048 + w4];
        s.x += t.x; s.y += t.y; s.z += t.z; s.w += t.w;
    }
    ((float4*)g_u)[i] = s;
}

// fold-reduce 16 floats over 32 lanes; lane l (<16) ends holding total of v[l]
__device__ __forceinline__ float fold16(float v[16], int lane) {
    #pragma unroll
    for (int i = 0; i < 16; i++)
        v[i] += __shfl_xor_sync(0xffffffffu, v[i], 16);
    #pragma unroll
    for (int i = 0; i < 8; i++) {
        float mn = (lane & 8) ? v[i+8] : v[i];
        float th = (lane & 8) ? v[i] : v[i+8];
        v[i] = mn + __shfl_xor_sync(0xffffffffu, th, 8);
    }
    #pragma unroll
    for (int i = 0; i < 4; i++) {
        float mn = (lane & 4) ? v[i+4] : v[i];
        float th = (lane & 4) ? v[i] : v[i+4];
        v[i] = mn + __shfl_xor_sync(0xffffffffu, th, 4);
    }
    #pragma unroll
    for (int i = 0; i < 2; i++) {
        float mn = (lane & 2) ? v[i+2] : v[i];
        float th = (lane & 2) ? v[i] : v[i+2];
        v[i] = mn + __shfl_xor_sync(0xffffffffu, th, 2);
    }
    {
        float mn = (lane & 1) ? v[1] : v[0];
        float th = (lane & 1) ? v[0] : v[1];
        v[0] = mn + __shfl_xor_sync(0xffffffffu, th, 1);
    }
    return v[0];
}

// ---------------- K3: op_out[b,o,h] = u[b,o,:].Wv[h,:] + bv[h]*W[b,o] -------
// grid (16 o, 16 hc of 32), 256 threads: 8 warps x 4 h rows
__global__ void __launch_bounds__(256) k3(const float* __restrict__ Wv,
                                          const float* __restrict__ bv) {
    __shared__ float4 u4[16*128];
    __shared__ float Wsh[16];
    int o = blockIdx.x, hc = blockIdx.y;
    for (int i = threadIdx.x; i < 16*128; i += 256) {
        int b = i >> 7, k4 = i & 127;
        u4[i] = ((const float4*)g_u)[((size_t)b*16 + o)*128 + k4];
    }
    if (threadIdx.x < 16) Wsh[threadIdx.x] = g_W[threadIdx.x*16 + o];
    __syncthreads();
    int wid = threadIdx.x >> 5, lane = threadIdx.x & 31;
    int h = hc*32 + wid*4;
    const float4* wv = ((const float4*)Wv) + (size_t)h * 128;
    float acc[4][16];
    #pragma unroll
    for (int r = 0; r < 4; r++)
        #pragma unroll
        for (int b = 0; b < 16; b++) acc[r][b] = 0.f;
    #pragma unroll
    for (int jj = 0; jj < 4; jj++) {
        int j = jj*32 + lane;
        float4 v0 = wv[j], v1 = wv[128+j], v2 = wv[256+j], v3 = wv[384+j];
        #pragma unroll
        for (int b = 0; b < 16; b++) {
            float4 uu = u4[b*128 + j];
            acc[0][b] += v0.x*uu.x + v0.y*uu.y + v0.z*uu.z + v0.w*uu.w;
            acc[1][b] += v1.x*uu.x + v1.y*uu.y + v1.z*uu.z + v1.w*uu.w;
            acc[2][b] += v2.x*uu.x + v2.y*uu.y + v2.z*uu.z + v2.w*uu.w;
            acc[3][b] += v3.x*uu.x + v3.y*uu.y + v3.z*uu.z + v3.w*uu.w;
        }
    }
    #pragma unroll
    for (int r = 0; r < 4; r++) {
        float t = fold16(acc[r], lane);
        if (lane < 16)
            g_opout[((size_t)lane*16 + o)*Hq + h + r] = t + bv[h + r] * Wsh[lane];
    }
}

// ---------------- K4: out[b,s,h] = sum_o softmax_o(L)[o]*op_out[b,o,h] ------
__global__ void __launch_bounds__(256) k4(float* __restrict__ out) {
    __shared__ __align__(16) float4 op4[16*128];
    int b = blockIdx.y, sc = blockIdx.x;
    for (int i = threadIdx.x; i < 16*128; i += 256)
        op4[i] = ((const float4*)g_opout)[(size_t)b*2048 + i];
    __syncthreads();
    int wid = threadIdx.x >> 5, lane = threadIdx.x & 31;
    for (int q = 0; q < 2; q++) {
        int s0 = sc*64 + wid*8 + q*4;
        size_t r0 = (size_t)b*Sq + s0;
        const float* lp = g_logits + (r0 + (lane & 3)) * 16;
        float e[16];
        float mx = -1e30f;
        #pragma unroll
        for (int o = 0; o < 16; o++) { e[o] = lp[o]; mx = fmaxf(mx, e[o]); }
        float sum = 0.f;
        #pragma unroll
        for (int o = 0; o < 16; o++) { e[o] = __expf(e[o] - mx); sum += e[o]; }
        float inv = 1.0f / sum;
        float ow0[16], ow1[16], ow2[16], ow3[16];
        #pragma unroll
        for (int o = 0; o < 16; o++) {
            float v = e[o] * inv;
            ow0[o] = __shfl_sync(0xffffffffu, v, 0, 4);
            ow1[o] = __shfl_sync(0xffffffffu, v, 1, 4);
            ow2[o] = __shfl_sync(0xffffffffu, v, 2, 4);
            ow3[o] = __shfl_sync(0xffffffffu, v, 3, 4);
        }
        ulonglong2* o2 = (ulonglong2*)(((float4*)out) + r0 * 128);
        #pragma unroll
        for (int jj = 0; jj < 4; jj++) {
            int j = jj*32 + lane;
            ull A0[2] = {0ull,0ull}, A1[2] = {0ull,0ull};
            ull A2[2] = {0ull,0ull}, A3[2] = {0ull,0ull};
            #pragma unroll
            for (int o = 0; o < 16; o++) {
                ulonglong2 kk = ((const ulonglong2*)op4)[o*128 + j];
                ull d0 = dup2(ow0[o]), d1 = dup2(ow1[o]);
                ull d2 = dup2(ow2[o]), d3 = dup2(ow3[o]);
                A0[0] = ffma2(d0, kk.x, A0[0]); A0[1] = ffma2(d0, kk.y, A0[1]);
                A1[0] = ffma2(d1, kk.x, A1[0]); A1[1] = ffma2(d1, kk.y, A1[1]);
                A2[0] = ffma2(d2, kk.x, A2[0]); A2[1] = ffma2(d2, kk.y, A2[1]);
                A3[0] = ffma2(d3, kk.x, A3[0]); A3[1] = ffma2(d3, kk.y, A3[1]);
            }
            o2[j]        = make_ulonglong2(A0[0], A0[1]);
            o2[128 + j]  = make_ulonglong2(A1[0], A1[1]);
            o2[256 + j]  = make_ulonglong2(A2[0], A2[1]);
            o2[384 + j]  = make_ulonglong2(A3[0], A3[1]);
        }
    }
}

// ---------------------------------------------------------------------------
extern "C" void kernel_launch(void* const* d_in, const int* in_sizes, int n_in,
                              void* d_out, int out_size) {
    const float* x     = (const float*)d_in[0];
    const float* Wv    = (const float*)d_in[1];
    const float* bv    = (const float*)d_in[2];
    const float* Wk    = (const float*)d_in[3];
    const float* bk    = (const float*)d_in[4];
    const float* Wq_op = (const float*)d_in[5];
    const float* bq_op = (const float*)d_in[6];
    const float* ops   = (const float*)d_in[7];
    (void)in_sizes; (void)n_in;
    float* out = (float*)d_out;
    float* oq_out = (out_size >= Bq*Sq*Hq + Oq*Hq) ? out + (size_t)Bq*Sq*Hq : nullptr;

    cudaFuncSetAttribute(k1, cudaFuncAttributeMaxDynamicSharedMemorySize,
                         SM_FLOATS * (int)sizeof(float));

    kzero<<<32, 256>>>();
    k0a<<<dim3(8, 16), 512>>>(Wq_op, ops);
    k0b<<<dim3(16, 16), 128>>>(Wk, bk, bq_op, oq_out);
    k1<<<512, 128, SM_FLOATS * sizeof(float)>>>(x);
    k2<<<dim3(32, 16), 256>>>(x, ops);
    ksum<<<128, 256>>>();
    k3<<<dim3(16, 16), 256>>>(Wv, bv);
    k4<<<dim3(32, 16), 256>>>(out);
}